// round 1
// baseline (speedup 1.0000x reference)
#include <cuda_runtime.h>

// Problem constants
// B=4, S=1024, P=1024, E=1024, H=16, D=64, NS=2048
// out = [4,1024,1024] (4194304 f32), present = [2,4,16,2048,64] (16777216 f32)

__device__ float g_qkv[4096 * 3072];   // [B*S, 3E]
__device__ float g_attn[4096 * 1024];  // merged-head attention output [B*S, E]

// ---------------------------------------------------------------------------
// SGEMM: C = A @ B + bias.  A[M,K], B[K,N] row-major. 128x128 tile, BK=8,
// 256 threads, 8x8 per thread split as 2x2 quadrants of 4x4 (conflict-free
// float4 fragment loads).
// ---------------------------------------------------------------------------
__global__ __launch_bounds__(256) void sgemm_bias_kernel(
    const float* __restrict__ A, const float* __restrict__ B,
    const float* __restrict__ bias, float* __restrict__ C,
    int M, int N, int K)
{
    __shared__ float As[8][128];
    __shared__ float Bs[8][128];

    const int tid = threadIdx.x;
    const int bm = blockIdx.y * 128;
    const int bn = blockIdx.x * 128;
    const int tx = tid & 15, ty = tid >> 4;

    const int ar = tid >> 1, ac = (tid & 1) << 2;   // A tile: 128 rows x 8 k
    const int br = tid >> 5, bc = (tid & 31) << 2;  // B tile: 8 k x 128 cols

    const float* Ap = A + (long)(bm + ar) * K + ac;
    const float* Bp = B + (long)br * N + bn + bc;

    float acc[2][2][4][4] = {};

    for (int k0 = 0; k0 < K; k0 += 8) {
        float4 av = *(const float4*)Ap;
        float4 bv = *(const float4*)Bp;
        Ap += 8;
        Bp += (long)8 * N;
        As[ac + 0][ar] = av.x;
        As[ac + 1][ar] = av.y;
        As[ac + 2][ar] = av.z;
        As[ac + 3][ar] = av.w;
        *(float4*)&Bs[br][bc] = bv;
        __syncthreads();
#pragma unroll
        for (int kk = 0; kk < 8; ++kk) {
            float a[2][4], b[2][4];
            *(float4*)a[0] = *(const float4*)&As[kk][ty * 4];
            *(float4*)a[1] = *(const float4*)&As[kk][64 + ty * 4];
            *(float4*)b[0] = *(const float4*)&Bs[kk][tx * 4];
            *(float4*)b[1] = *(const float4*)&Bs[kk][64 + tx * 4];
#pragma unroll
            for (int qr = 0; qr < 2; qr++)
#pragma unroll
                for (int qc = 0; qc < 2; qc++)
#pragma unroll
                    for (int i = 0; i < 4; i++)
#pragma unroll
                        for (int j = 0; j < 4; j++)
                            acc[qr][qc][i][j] += a[qr][i] * b[qc][j];
        }
        __syncthreads();
    }

#pragma unroll
    for (int qr = 0; qr < 2; qr++)
#pragma unroll
        for (int i = 0; i < 4; i++) {
            int row = bm + qr * 64 + ty * 4 + i;
#pragma unroll
            for (int qc = 0; qc < 2; qc++) {
                int col = bn + qc * 64 + tx * 4;
                float4 r;
                r.x = acc[qr][qc][i][0] + bias[col + 0];
                r.y = acc[qr][qc][i][1] + bias[col + 1];
                r.z = acc[qr][qc][i][2] + bias[col + 2];
                r.w = acc[qr][qc][i][3] + bias[col + 3];
                *(float4*)&C[(long)row * N + col] = r;
            }
        }
}

// ---------------------------------------------------------------------------
// present = concat(layer_past, new K/V).  present layout [2,4,16,2048,64].
// One float4 per thread.
// ---------------------------------------------------------------------------
__global__ __launch_bounds__(256) void copy_present_kernel(
    const float* __restrict__ past, const float* __restrict__ qkv,
    float* __restrict__ present)
{
    int i4 = blockIdx.x * 256 + threadIdx.x;  // 0 .. 4194303
    int d4 = i4 & 15;
    int t = i4 >> 4;
    int p = t & 2047; t >>= 11;
    int h = t & 15;   t >>= 4;
    int b = t & 3;    t >>= 2;
    int kv = t;       // 0 = K, 1 = V

    float4 v;
    if (p < 1024) {
        v = *(const float4*)&past[(((long)(kv * 4 + b) * 16 + h) * 1024 + p) * 64 + d4 * 4];
    } else {
        int s = p - 1024;
        v = *(const float4*)&qkv[((long)b * 1024 + s) * 3072 + (kv + 1) * 1024 + h * 64 + d4 * 4];
    }
    *(float4*)&present[(long)i4 * 4] = v;
}

// ---------------------------------------------------------------------------
// Flash-style causal attention.
// Block = (b, h, qtile of 128 queries). 256 threads as 16x16; each thread owns
// an 8x4 micro-tile (rows ty*8+i, cols tx*4+j). Rows of a tile live entirely in
// one half-warp -> online softmax row reductions via 16-lane shfl_xor.
// K/V read from `present` (global rows: query = 1024 + s, keys 0..2047).
// ---------------------------------------------------------------------------
__global__ __launch_bounds__(256) void attn_kernel(
    const float* __restrict__ qkv,
    const float* __restrict__ present,
    float* __restrict__ aout)
{
    extern __shared__ float sm[];
    float* Qs = sm;                  // [128][65]  (pre-scaled by 0.125)
    float* Ks = Qs + 128 * 65;       // [64][65]
    float* Vs = Ks + 64 * 65;        // [64][65]
    float* Ps = Vs + 64 * 65;        // [128][65]

    const int tid = threadIdx.x;
    const int qt = blockIdx.x & 7;
    const int h  = (blockIdx.x >> 3) & 15;
    const int b  = blockIdx.x >> 7;
    const int tx = tid & 15, ty = tid >> 4;

    // Load Q tile (128 x 64), scale by 1/sqrt(64)
    {
        const float* qbase = qkv + ((long)b * 1024 + qt * 128) * 3072 + h * 64;
#pragma unroll
        for (int l = 0; l < 8; ++l) {
            int idx = l * 256 + tid;          // 128 rows x 16 float4
            int r = idx >> 4, c = (idx & 15) * 4;
            float4 v = *(const float4*)&qbase[(long)r * 3072 + c];
            Qs[r * 65 + c + 0] = v.x * 0.125f;
            Qs[r * 65 + c + 1] = v.y * 0.125f;
            Qs[r * 65 + c + 2] = v.z * 0.125f;
            Qs[r * 65 + c + 3] = v.w * 0.125f;
        }
    }

    const float* kbase = present + (long)(b * 16 + h) * (2048 * 64);
    const float* vbase = kbase + (long)4 * 16 * 2048 * 64;  // present[1] block

    float O[8][4] = {};
    float mrow[8], lrow[8];
#pragma unroll
    for (int i = 0; i < 8; i++) { mrow[i] = -1e30f; lrow[i] = 0.f; }

    const int diag0 = 16 + 2 * qt;      // first partially-masked key tile
    const int nkt = diag0 + 2;          // total key tiles for this q tile

    for (int kt = 0; kt < nkt; ++kt) {
        // Load K,V tiles (64 x 64 each) to registers, coalesced.
        float4 kreg[4], vreg[4];
        {
            const float* kp = kbase + (long)kt * 64 * 64;
            const float* vp = vbase + (long)kt * 64 * 64;
#pragma unroll
            for (int l = 0; l < 4; ++l) {
                int idx = l * 256 + tid;  // 64 rows x 16 float4
                kreg[l] = *(const float4*)&kp[idx * 4];
                vreg[l] = *(const float4*)&vp[idx * 4];
            }
        }
        // Stage K (V staged later, after previous PV readers are past sync1)
#pragma unroll
        for (int l = 0; l < 4; ++l) {
            int idx = l * 256 + tid;
            int r = idx >> 4, c = (idx & 15) * 4;
            Ks[r * 65 + c + 0] = kreg[l].x;
            Ks[r * 65 + c + 1] = kreg[l].y;
            Ks[r * 65 + c + 2] = kreg[l].z;
            Ks[r * 65 + c + 3] = kreg[l].w;
        }
        __syncthreads();  // sync1: K ready; prior-iteration PV reads complete

        // S = Q K^T (scaled), 8x4 per thread
        float s[8][4] = {};
#pragma unroll 4
        for (int kk = 0; kk < 64; ++kk) {
            float qv[8], kv[4];
#pragma unroll
            for (int i = 0; i < 8; i++) qv[i] = Qs[(ty * 8 + i) * 65 + kk];
#pragma unroll
            for (int j = 0; j < 4; j++) kv[j] = Ks[(tx * 4 + j) * 65 + kk];
#pragma unroll
            for (int i = 0; i < 8; i++)
#pragma unroll
                for (int j = 0; j < 4; j++)
                    s[i][j] += qv[i] * kv[j];
        }

        // Causal mask: key j allowed iff j <= 1024 + query_index
        if (kt >= diag0) {
#pragma unroll
            for (int i = 0; i < 8; i++) {
                int qglob = 1024 + qt * 128 + ty * 8 + i;
#pragma unroll
                for (int j = 0; j < 4; j++) {
                    int kglob = kt * 64 + tx * 4 + j;
                    if (kglob > qglob) s[i][j] = -10000.0f;
                }
            }
        }

        // Online softmax: rows owned by 16-lane half-warp groups
#pragma unroll
        for (int i = 0; i < 8; i++) {
            float mt = fmaxf(fmaxf(s[i][0], s[i][1]), fmaxf(s[i][2], s[i][3]));
#pragma unroll
            for (int m = 1; m < 16; m <<= 1)
                mt = fmaxf(mt, __shfl_xor_sync(0xffffffffu, mt, m));
            float mn = fmaxf(mrow[i], mt);
            float corr = __expf(mrow[i] - mn);
            mrow[i] = mn;
            float rs = 0.f;
#pragma unroll
            for (int j = 0; j < 4; j++) {
                float p = __expf(s[i][j] - mn);
                s[i][j] = p;
                rs += p;
            }
#pragma unroll
            for (int m = 1; m < 16; m <<= 1)
                rs += __shfl_xor_sync(0xffffffffu, rs, m);
            lrow[i] = lrow[i] * corr + rs;
#pragma unroll
            for (int j = 0; j < 4; j++) O[i][j] *= corr;
        }

        // Stage P and V
#pragma unroll
        for (int i = 0; i < 8; i++)
#pragma unroll
            for (int j = 0; j < 4; j++)
                Ps[(ty * 8 + i) * 65 + tx * 4 + j] = s[i][j];
#pragma unroll
        for (int l = 0; l < 4; ++l) {
            int idx = l * 256 + tid;
            int r = idx >> 4, c = (idx & 15) * 4;
            Vs[r * 65 + c + 0] = vreg[l].x;
            Vs[r * 65 + c + 1] = vreg[l].y;
            Vs[r * 65 + c + 2] = vreg[l].z;
            Vs[r * 65 + c + 3] = vreg[l].w;
        }
        __syncthreads();  // sync2: P,V ready

        // O += P @ V
#pragma unroll 4
        for (int kk = 0; kk < 64; ++kk) {
            float pv[8], vv[4];
#pragma unroll
            for (int i = 0; i < 8; i++) pv[i] = Ps[(ty * 8 + i) * 65 + kk];
#pragma unroll
            for (int j = 0; j < 4; j++) vv[j] = Vs[kk * 65 + tx * 4 + j];
#pragma unroll
            for (int i = 0; i < 8; i++)
#pragma unroll
                for (int j = 0; j < 4; j++)
                    O[i][j] += pv[i] * vv[j];
        }
        // No sync needed here: next iteration only writes Ks before sync1,
        // which this PV phase never reads.
    }

    // Epilogue: normalize, write merged-head layout [b*1024+s][h*64+d]
    float* obase = aout + ((long)b * 1024 + qt * 128) * 1024 + h * 64;
#pragma unroll
    for (int i = 0; i < 8; i++) {
        float inv = 1.0f / lrow[i];
        float4 r;
        r.x = O[i][0] * inv;
        r.y = O[i][1] * inv;
        r.z = O[i][2] * inv;
        r.w = O[i][3] * inv;
        *(float4*)&obase[(long)(ty * 8 + i) * 1024 + tx * 4] = r;
    }
}

// ---------------------------------------------------------------------------
extern "C" void kernel_launch(void* const* d_in, const int* in_sizes, int n_in,
                              void* d_out, int out_size)
{
    const float* x      = (const float*)d_in[0];
    const float* past   = (const float*)d_in[1];
    const float* w_attn = (const float*)d_in[2];
    const float* b_attn = (const float*)d_in[3];
    const float* w_proj = (const float*)d_in[4];
    const float* b_proj = (const float*)d_in[5];

    float* out = (float*)d_out;                 // [4,1024,1024]
    float* present = out + 4194304;             // [2,4,16,2048,64]

    float* qkv_p = nullptr;
    float* attn_p = nullptr;
    cudaGetSymbolAddress((void**)&qkv_p, g_qkv);
    cudaGetSymbolAddress((void**)&attn_p, g_attn);

    // 1) QKV projection: [4096,1024] @ [1024,3072] + bias
    {
        dim3 grid(3072 / 128, 4096 / 128);
        sgemm_bias_kernel<<<grid, 256>>>(x, w_attn, b_attn, qkv_p, 4096, 3072, 1024);
    }

    // 2) Build present (also the K/V source for attention)
    copy_present_kernel<<<4194304 / 256, 256>>>(past, qkv_p, present);

    // 3) Attention
    {
        int smem = (128 * 65 + 64 * 65 + 64 * 65 + 128 * 65) * (int)sizeof(float);
        cudaFuncSetAttribute(attn_kernel,
                             cudaFuncAttributeMaxDynamicSharedMemorySize, smem);
        attn_kernel<<<512, 256, smem>>>(qkv_p, present, attn_p);
    }

    // 4) Output projection: [4096,1024] @ [1024,1024] + bias
    {
        dim3 grid(1024 / 128, 4096 / 128);
        sgemm_bias_kernel<<<grid, 256>>>(attn_p, w_proj, b_proj, out, 4096, 1024, 1024);
    }
}

// round 2
// speedup vs baseline: 2.8443x; 2.8443x over previous
#include <cuda_runtime.h>

// B=4, S=1024, P=1024, E=1024, H=16, D=64, NS=2048
// out = [4,1024,1024] f32, present = [2,4,16,2048,64] f32 (packed after out)

__device__ float g_qkv[4096 * 3072];   // [B*S, 3E]
__device__ float g_attn[4096 * 1024];  // merged-head attention output

__device__ __forceinline__ unsigned f2tf(float x) {
    unsigned u;
    asm("cvt.rna.tf32.f32 %0, %1;" : "=r"(u) : "f"(x));
    return u;
}

__device__ __forceinline__ void mma_tf32(float c[4], unsigned a0, unsigned a1,
                                         unsigned a2, unsigned a3,
                                         unsigned b0, unsigned b1) {
    asm volatile(
        "mma.sync.aligned.m16n8k8.row.col.f32.tf32.tf32.f32 "
        "{%0,%1,%2,%3}, {%4,%5,%6,%7}, {%8,%9}, {%0,%1,%2,%3};\n"
        : "+f"(c[0]), "+f"(c[1]), "+f"(c[2]), "+f"(c[3])
        : "r"(a0), "r"(a1), "r"(a2), "r"(a3), "r"(b0), "r"(b1));
}

// ---------------------------------------------------------------------------
// tf32 GEMM: C = A @ B + bias. A[M,K], B[K,N] row-major.
// Block 128x128, BK=16, 256 threads (8 warps as 2x4; warp tile 64x32).
// Smem: As[k][m] / Bs[k][n], stride 136 (conflict-free fragment LDS),
// double-buffered.
// ---------------------------------------------------------------------------
#define GST 136
__global__ __launch_bounds__(256, 2) void gemm_tf32_kernel(
    const float* __restrict__ A, const float* __restrict__ B,
    const float* __restrict__ bias, float* __restrict__ C,
    int M, int N, int K)
{
    __shared__ float As[2][16][GST];
    __shared__ float Bs[2][16][GST];

    const int tid = threadIdx.x;
    const int lane = tid & 31;
    const int wid = tid >> 5;
    const int wm = wid & 1;          // 0..1 -> 64 rows
    const int wn = wid >> 1;         // 0..3 -> 32 cols
    const int bm = blockIdx.y * 128;
    const int bn = blockIdx.x * 128;

    const int ar = tid >> 1, ak = (tid & 1) << 3;    // A: 128 rows x (2x float4 k)
    const int bk = tid >> 4, bnc = (tid & 15) << 3;  // B: 16 k x (2x float4 n)

    const float* Ap = A + (long)(bm + ar) * K + ak;
    const float* Bp = B + (long)bk * N + bn + bnc;

    float acc[4][4][4] = {};

    // preload tile 0
    float4 av0 = *(const float4*)Ap;
    float4 av1 = *(const float4*)(Ap + 4);
    float4 bv0 = *(const float4*)Bp;
    float4 bv1 = *(const float4*)(Bp + 4);

    int buf = 0;
    {
        As[0][ak + 0][ar] = __uint_as_float(f2tf(av0.x));
        As[0][ak + 1][ar] = __uint_as_float(f2tf(av0.y));
        As[0][ak + 2][ar] = __uint_as_float(f2tf(av0.z));
        As[0][ak + 3][ar] = __uint_as_float(f2tf(av0.w));
        As[0][ak + 4][ar] = __uint_as_float(f2tf(av1.x));
        As[0][ak + 5][ar] = __uint_as_float(f2tf(av1.y));
        As[0][ak + 6][ar] = __uint_as_float(f2tf(av1.z));
        As[0][ak + 7][ar] = __uint_as_float(f2tf(av1.w));
        float4 t0, t1;
        t0.x = __uint_as_float(f2tf(bv0.x)); t0.y = __uint_as_float(f2tf(bv0.y));
        t0.z = __uint_as_float(f2tf(bv0.z)); t0.w = __uint_as_float(f2tf(bv0.w));
        t1.x = __uint_as_float(f2tf(bv1.x)); t1.y = __uint_as_float(f2tf(bv1.y));
        t1.z = __uint_as_float(f2tf(bv1.z)); t1.w = __uint_as_float(f2tf(bv1.w));
        *(float4*)&Bs[0][bk][bnc] = t0;
        *(float4*)&Bs[0][bk][bnc + 4] = t1;
    }
    __syncthreads();

    const int nIter = K / 16;
    for (int it = 0; it < nIter; ++it) {
        if (it + 1 < nIter) {
            Ap += 16;
            Bp += (long)16 * N;
            av0 = *(const float4*)Ap;
            av1 = *(const float4*)(Ap + 4);
            bv0 = *(const float4*)Bp;
            bv1 = *(const float4*)(Bp + 4);
        }
        // compute on buf
#pragma unroll
        for (int kk = 0; kk < 2; ++kk) {
            const int k = kk * 8;
            unsigned af[4][4];
#pragma unroll
            for (int mt = 0; mt < 4; ++mt) {
                int m = wm * 64 + mt * 16 + (lane >> 2);
                af[mt][0] = __float_as_uint(As[buf][k + (lane & 3)][m]);
                af[mt][1] = __float_as_uint(As[buf][k + (lane & 3)][m + 8]);
                af[mt][2] = __float_as_uint(As[buf][k + (lane & 3) + 4][m]);
                af[mt][3] = __float_as_uint(As[buf][k + (lane & 3) + 4][m + 8]);
            }
#pragma unroll
            for (int nt = 0; nt < 4; ++nt) {
                int n = wn * 32 + nt * 8 + (lane >> 2);
                unsigned b0 = __float_as_uint(Bs[buf][k + (lane & 3)][n]);
                unsigned b1 = __float_as_uint(Bs[buf][k + (lane & 3) + 4][n]);
#pragma unroll
                for (int mt = 0; mt < 4; ++mt)
                    mma_tf32(acc[mt][nt], af[mt][0], af[mt][1], af[mt][2], af[mt][3], b0, b1);
            }
        }
        if (it + 1 < nIter) {
            int nb = buf ^ 1;
            As[nb][ak + 0][ar] = __uint_as_float(f2tf(av0.x));
            As[nb][ak + 1][ar] = __uint_as_float(f2tf(av0.y));
            As[nb][ak + 2][ar] = __uint_as_float(f2tf(av0.z));
            As[nb][ak + 3][ar] = __uint_as_float(f2tf(av0.w));
            As[nb][ak + 4][ar] = __uint_as_float(f2tf(av1.x));
            As[nb][ak + 5][ar] = __uint_as_float(f2tf(av1.y));
            As[nb][ak + 6][ar] = __uint_as_float(f2tf(av1.z));
            As[nb][ak + 7][ar] = __uint_as_float(f2tf(av1.w));
            float4 t0, t1;
            t0.x = __uint_as_float(f2tf(bv0.x)); t0.y = __uint_as_float(f2tf(bv0.y));
            t0.z = __uint_as_float(f2tf(bv0.z)); t0.w = __uint_as_float(f2tf(bv0.w));
            t1.x = __uint_as_float(f2tf(bv1.x)); t1.y = __uint_as_float(f2tf(bv1.y));
            t1.z = __uint_as_float(f2tf(bv1.z)); t1.w = __uint_as_float(f2tf(bv1.w));
            *(float4*)&Bs[nb][bk][bnc] = t0;
            *(float4*)&Bs[nb][bk][bnc + 4] = t1;
            __syncthreads();
            buf = nb;
        }
    }

    // epilogue
#pragma unroll
    for (int mt = 0; mt < 4; ++mt) {
        int row0 = bm + wm * 64 + mt * 16 + (lane >> 2);
#pragma unroll
        for (int nt = 0; nt < 4; ++nt) {
            int col = bn + wn * 32 + nt * 8 + 2 * (lane & 3);
            float2 bv = *(const float2*)&bias[col];
            float2 v0, v1;
            v0.x = acc[mt][nt][0] + bv.x; v0.y = acc[mt][nt][1] + bv.y;
            v1.x = acc[mt][nt][2] + bv.x; v1.y = acc[mt][nt][3] + bv.y;
            *(float2*)&C[(long)row0 * N + col] = v0;
            *(float2*)&C[(long)(row0 + 8) * N + col] = v1;
        }
    }
}

// ---------------------------------------------------------------------------
// present = concat(layer_past, new K/V). present layout [2,4,16,2048,64].
// ---------------------------------------------------------------------------
__global__ __launch_bounds__(256) void copy_present_kernel(
    const float* __restrict__ past, const float* __restrict__ qkv,
    float* __restrict__ present)
{
    int i4 = blockIdx.x * 256 + threadIdx.x;  // 0 .. 4194303
    int d4 = i4 & 15;
    int t = i4 >> 4;
    int p = t & 2047; t >>= 11;
    int h = t & 15;   t >>= 4;
    int b = t & 3;    t >>= 2;
    int kv = t;

    float4 v;
    if (p < 1024) {
        v = *(const float4*)&past[(((long)(kv * 4 + b) * 16 + h) * 1024 + p) * 64 + d4 * 4];
    } else {
        int s = p - 1024;
        v = *(const float4*)&qkv[((long)b * 1024 + s) * 3072 + (kv + 1) * 1024 + h * 64 + d4 * 4];
    }
    *(float4*)&present[(long)i4 * 4] = v;
}

// ---------------------------------------------------------------------------
// Flash attention with tf32 mma. Block = (b,h,qtile of 128). 256 threads,
// 8 warps; warp w owns query rows [16w, 16w+16).
// Smem strides: Q/K/P = 68, V = 72 (conflict-free fragment LDS).
// ---------------------------------------------------------------------------
#define QKP 68
#define VST 72
__global__ __launch_bounds__(256, 2) void attn_kernel(
    const float* __restrict__ qkv,
    const float* __restrict__ present,
    float* __restrict__ aout)
{
    extern __shared__ float sm[];
    float* Qs = sm;                    // [128][68]
    float* Ks = Qs + 128 * QKP;        // [64][68]
    float* Ps = Ks + 64 * QKP;         // [128][68]
    float* Vs = Ps + 128 * QKP;        // [64][72]

    const int tid = threadIdx.x;
    const int lane = tid & 31;
    const int w = tid >> 5;
    const int qt = blockIdx.x & 7;
    const int h  = (blockIdx.x >> 3) & 15;
    const int b  = blockIdx.x >> 7;

    // Load Q tile (128 x 64), scale by 1/8, convert to tf32
    {
        const float* qbase = qkv + ((long)b * 1024 + qt * 128) * 3072 + h * 64;
#pragma unroll
        for (int l = 0; l < 8; ++l) {
            int idx = l * 256 + tid;            // 128 rows x 16 float4
            int r = idx >> 4, c = (idx & 15) * 4;
            float4 v = *(const float4*)&qbase[(long)r * 3072 + c];
            Qs[r * QKP + c + 0] = __uint_as_float(f2tf(v.x * 0.125f));
            Qs[r * QKP + c + 1] = __uint_as_float(f2tf(v.y * 0.125f));
            Qs[r * QKP + c + 2] = __uint_as_float(f2tf(v.z * 0.125f));
            Qs[r * QKP + c + 3] = __uint_as_float(f2tf(v.w * 0.125f));
        }
    }
    __syncthreads();

    // Hoist Q fragments into registers (constant across key tiles)
    unsigned qf[8][4];
    {
        int r = 16 * w + (lane >> 2);
#pragma unroll
        for (int kk = 0; kk < 8; ++kk) {
            int k = kk * 8 + (lane & 3);
            qf[kk][0] = __float_as_uint(Qs[r * QKP + k]);
            qf[kk][1] = __float_as_uint(Qs[(r + 8) * QKP + k]);
            qf[kk][2] = __float_as_uint(Qs[r * QKP + k + 4]);
            qf[kk][3] = __float_as_uint(Qs[(r + 8) * QKP + k + 4]);
        }
    }

    const float* kbase = present + (long)(b * 16 + h) * (2048 * 64);
    const float* vbase = kbase + (long)4 * 16 * 2048 * 64;

    float o[8][4] = {};
    float m0 = -1e30f, m1 = -1e30f, l0 = 0.f, l1 = 0.f;

    const int diag0 = 16 + 2 * qt;
    const int nkt = diag0 + 2;

    for (int kt = 0; kt < nkt; ++kt) {
        __syncthreads();  // prior tile's Ks/Vs reads complete
        {
            const float* kp = kbase + (long)kt * 64 * 64;
            const float* vp = vbase + (long)kt * 64 * 64;
#pragma unroll
            for (int l = 0; l < 4; ++l) {
                int idx = l * 256 + tid;        // 64 rows x 16 float4
                int r = idx >> 4, c = (idx & 15) * 4;
                float4 kv4 = *(const float4*)&kp[idx * 4];
                float4 vv4 = *(const float4*)&vp[idx * 4];
                Ks[r * QKP + c + 0] = __uint_as_float(f2tf(kv4.x));
                Ks[r * QKP + c + 1] = __uint_as_float(f2tf(kv4.y));
                Ks[r * QKP + c + 2] = __uint_as_float(f2tf(kv4.z));
                Ks[r * QKP + c + 3] = __uint_as_float(f2tf(kv4.w));
                Vs[r * VST + c + 0] = __uint_as_float(f2tf(vv4.x));
                Vs[r * VST + c + 1] = __uint_as_float(f2tf(vv4.y));
                Vs[r * VST + c + 2] = __uint_as_float(f2tf(vv4.z));
                Vs[r * VST + c + 3] = __uint_as_float(f2tf(vv4.w));
            }
        }
        __syncthreads();

        // S = Q K^T : 8 n-tiles of 8 keys, 8 k-steps over d
        float s[8][4] = {};
#pragma unroll
        for (int kk = 0; kk < 8; ++kk) {
            int k = kk * 8 + (lane & 3);
#pragma unroll
            for (int nt = 0; nt < 8; ++nt) {
                int n = nt * 8 + (lane >> 2);
                unsigned b0 = __float_as_uint(Ks[n * QKP + k]);
                unsigned b1 = __float_as_uint(Ks[n * QKP + k + 4]);
                mma_tf32(s[nt], qf[kk][0], qf[kk][1], qf[kk][2], qf[kk][3], b0, b1);
            }
        }

        // causal mask
        if (kt >= diag0) {
            int q0 = 1024 + qt * 128 + 16 * w + (lane >> 2);
            int q1 = q0 + 8;
#pragma unroll
            for (int nt = 0; nt < 8; ++nt) {
                int kc = kt * 64 + nt * 8 + 2 * (lane & 3);
                if (kc > q0)     s[nt][0] = -10000.0f;
                if (kc + 1 > q0) s[nt][1] = -10000.0f;
                if (kc > q1)     s[nt][2] = -10000.0f;
                if (kc + 1 > q1) s[nt][3] = -10000.0f;
            }
        }

        // online softmax (rows r0 = vals [0],[1]; r1 = vals [2],[3])
        {
            float mt0 = -1e30f, mt1 = -1e30f;
#pragma unroll
            for (int nt = 0; nt < 8; ++nt) {
                mt0 = fmaxf(mt0, fmaxf(s[nt][0], s[nt][1]));
                mt1 = fmaxf(mt1, fmaxf(s[nt][2], s[nt][3]));
            }
            mt0 = fmaxf(mt0, __shfl_xor_sync(0xffffffffu, mt0, 1));
            mt0 = fmaxf(mt0, __shfl_xor_sync(0xffffffffu, mt0, 2));
            mt1 = fmaxf(mt1, __shfl_xor_sync(0xffffffffu, mt1, 1));
            mt1 = fmaxf(mt1, __shfl_xor_sync(0xffffffffu, mt1, 2));
            float mn0 = fmaxf(m0, mt0), mn1 = fmaxf(m1, mt1);
            float c0 = __expf(m0 - mn0), c1 = __expf(m1 - mn1);
            m0 = mn0; m1 = mn1;
            float rs0 = 0.f, rs1 = 0.f;
#pragma unroll
            for (int nt = 0; nt < 8; ++nt) {
                s[nt][0] = __expf(s[nt][0] - mn0);
                s[nt][1] = __expf(s[nt][1] - mn0);
                s[nt][2] = __expf(s[nt][2] - mn1);
                s[nt][3] = __expf(s[nt][3] - mn1);
                rs0 += s[nt][0] + s[nt][1];
                rs1 += s[nt][2] + s[nt][3];
            }
            rs0 += __shfl_xor_sync(0xffffffffu, rs0, 1);
            rs0 += __shfl_xor_sync(0xffffffffu, rs0, 2);
            rs1 += __shfl_xor_sync(0xffffffffu, rs1, 1);
            rs1 += __shfl_xor_sync(0xffffffffu, rs1, 2);
            l0 = l0 * c0 + rs0;
            l1 = l1 * c1 + rs1;
#pragma unroll
            for (int dt = 0; dt < 8; ++dt) {
                o[dt][0] *= c0; o[dt][1] *= c0;
                o[dt][2] *= c1; o[dt][3] *= c1;
            }
        }

        // stage P (warp-private rows) as tf32
        {
            int r0 = 16 * w + (lane >> 2);
#pragma unroll
            for (int nt = 0; nt < 8; ++nt) {
                int c = nt * 8 + 2 * (lane & 3);
                float2 p0, p1;
                p0.x = __uint_as_float(f2tf(s[nt][0]));
                p0.y = __uint_as_float(f2tf(s[nt][1]));
                p1.x = __uint_as_float(f2tf(s[nt][2]));
                p1.y = __uint_as_float(f2tf(s[nt][3]));
                *(float2*)&Ps[r0 * QKP + c] = p0;
                *(float2*)&Ps[(r0 + 8) * QKP + c] = p1;
            }
        }
        __syncwarp();

        // O += P @ V : 8 k-steps over keys, 8 n-tiles over d
        {
            int r = 16 * w + (lane >> 2);
#pragma unroll
            for (int kk = 0; kk < 8; ++kk) {
                int k = kk * 8 + (lane & 3);
                unsigned a0 = __float_as_uint(Ps[r * QKP + k]);
                unsigned a1 = __float_as_uint(Ps[(r + 8) * QKP + k]);
                unsigned a2 = __float_as_uint(Ps[r * QKP + k + 4]);
                unsigned a3 = __float_as_uint(Ps[(r + 8) * QKP + k + 4]);
#pragma unroll
                for (int dt = 0; dt < 8; ++dt) {
                    int n = dt * 8 + (lane >> 2);
                    unsigned b0 = __float_as_uint(Vs[k * VST + n]);
                    unsigned b1 = __float_as_uint(Vs[(k + 4) * VST + n]);
                    mma_tf32(o[dt], a0, a1, a2, a3, b0, b1);
                }
            }
        }
    }

    // epilogue
    {
        float inv0 = 1.0f / l0, inv1 = 1.0f / l1;
        int row0 = b * 1024 + qt * 128 + 16 * w + (lane >> 2);
        float* ob = aout + (long)row0 * 1024 + h * 64;
#pragma unroll
        for (int dt = 0; dt < 8; ++dt) {
            int c = dt * 8 + 2 * (lane & 3);
            float2 v0, v1;
            v0.x = o[dt][0] * inv0; v0.y = o[dt][1] * inv0;
            v1.x = o[dt][2] * inv1; v1.y = o[dt][3] * inv1;
            *(float2*)&ob[c] = v0;
            *(float2*)&ob[(long)8 * 1024 + c] = v1;
        }
    }
}

// ---------------------------------------------------------------------------
extern "C" void kernel_launch(void* const* d_in, const int* in_sizes, int n_in,
                              void* d_out, int out_size)
{
    const float* x      = (const float*)d_in[0];
    const float* past   = (const float*)d_in[1];
    const float* w_attn = (const float*)d_in[2];
    const float* b_attn = (const float*)d_in[3];
    const float* w_proj = (const float*)d_in[4];
    const float* b_proj = (const float*)d_in[5];

    float* out = (float*)d_out;
    float* present = out + 4194304;

    float* qkv_p = nullptr;
    float* attn_p = nullptr;
    cudaGetSymbolAddress((void**)&qkv_p, g_qkv);
    cudaGetSymbolAddress((void**)&attn_p, g_attn);

    // 1) QKV projection
    {
        dim3 grid(3072 / 128, 4096 / 128);
        gemm_tf32_kernel<<<grid, 256>>>(x, w_attn, b_attn, qkv_p, 4096, 3072, 1024);
    }

    // 2) present (K/V source)
    copy_present_kernel<<<4194304 / 256, 256>>>(past, qkv_p, present);

    // 3) attention
    {
        int smem = (128 * QKP + 64 * QKP + 128 * QKP + 64 * VST) * (int)sizeof(float);
        cudaFuncSetAttribute(attn_kernel,
                             cudaFuncAttributeMaxDynamicSharedMemorySize, smem);
        attn_kernel<<<512, 256, smem>>>(qkv_p, present, attn_p);
    }

    // 4) output projection
    {
        dim3 grid(1024 / 128, 4096 / 128);
        gemm_tf32_kernel<<<grid, 256>>>(attn_p, w_proj, b_proj, out, 4096, 1024, 1024);
    }
}

// round 4
// speedup vs baseline: 2.9215x; 1.0272x over previous
#include <cuda_runtime.h>

// B=4, S=1024, P=1024, E=1024, H=16, D=64, NS=2048
// out = [4,1024,1024] f32, present = [2,4,16,2048,64] f32 (packed after out)

__device__ float g_qkv[4096 * 3072];   // [B*S, 3E]
__device__ float g_attn[4096 * 1024];  // merged-head attention output
__device__ float g_kvt[2 * 4 * 16 * 2048 * 64];  // tf32-rounded K/V, present layout

__device__ __forceinline__ unsigned f2tf(float x) {
    unsigned u;
    asm("cvt.rna.tf32.f32 %0, %1;" : "=r"(u) : "f"(x));
    return u;
}

__device__ __forceinline__ float ex2(float x) {
    float y;
    asm("ex2.approx.ftz.f32 %0, %1;" : "=f"(y) : "f"(x));
    return y;
}

__device__ __forceinline__ void mma_tf32(float c[4], unsigned a0, unsigned a1,
                                         unsigned a2, unsigned a3,
                                         unsigned b0, unsigned b1) {
    asm volatile(
        "mma.sync.aligned.m16n8k8.row.col.f32.tf32.tf32.f32 "
        "{%0,%1,%2,%3}, {%4,%5,%6,%7}, {%8,%9}, {%0,%1,%2,%3};\n"
        : "+f"(c[0]), "+f"(c[1]), "+f"(c[2]), "+f"(c[3])
        : "r"(a0), "r"(a1), "r"(a2), "r"(a3), "r"(b0), "r"(b1));
}

__device__ __forceinline__ void cp16(unsigned dst_smem, const void* src) {
    asm volatile("cp.async.ca.shared.global [%0], [%1], 16;\n"
                 :: "r"(dst_smem), "l"(src));
}
__device__ __forceinline__ void cp_commit() {
    asm volatile("cp.async.commit_group;\n");
}
__device__ __forceinline__ void cp_wait1() {
    asm volatile("cp.async.wait_group 1;\n");
}

// ---------------------------------------------------------------------------
// tf32 GEMM (unchanged from R2): C = A @ B + bias. 128x128, BK=16, 8 warps.
// ---------------------------------------------------------------------------
#define GST 136
__global__ __launch_bounds__(256, 2) void gemm_tf32_kernel(
    const float* __restrict__ A, const float* __restrict__ B,
    const float* __restrict__ bias, float* __restrict__ C,
    int M, int N, int K)
{
    __shared__ float As[2][16][GST];
    __shared__ float Bs[2][16][GST];

    const int tid = threadIdx.x;
    const int lane = tid & 31;
    const int wid = tid >> 5;
    const int wm = wid & 1;
    const int wn = wid >> 1;
    const int bm = blockIdx.y * 128;
    const int bn = blockIdx.x * 128;

    const int ar = tid >> 1, ak = (tid & 1) << 3;
    const int bk = tid >> 4, bnc = (tid & 15) << 3;

    const float* Ap = A + (long)(bm + ar) * K + ak;
    const float* Bp = B + (long)bk * N + bn + bnc;

    float acc[4][4][4] = {};

    float4 av0 = *(const float4*)Ap;
    float4 av1 = *(const float4*)(Ap + 4);
    float4 bv0 = *(const float4*)Bp;
    float4 bv1 = *(const float4*)(Bp + 4);

    int buf = 0;
    {
        As[0][ak + 0][ar] = __uint_as_float(f2tf(av0.x));
        As[0][ak + 1][ar] = __uint_as_float(f2tf(av0.y));
        As[0][ak + 2][ar] = __uint_as_float(f2tf(av0.z));
        As[0][ak + 3][ar] = __uint_as_float(f2tf(av0.w));
        As[0][ak + 4][ar] = __uint_as_float(f2tf(av1.x));
        As[0][ak + 5][ar] = __uint_as_float(f2tf(av1.y));
        As[0][ak + 6][ar] = __uint_as_float(f2tf(av1.z));
        As[0][ak + 7][ar] = __uint_as_float(f2tf(av1.w));
        float4 t0, t1;
        t0.x = __uint_as_float(f2tf(bv0.x)); t0.y = __uint_as_float(f2tf(bv0.y));
        t0.z = __uint_as_float(f2tf(bv0.z)); t0.w = __uint_as_float(f2tf(bv0.w));
        t1.x = __uint_as_float(f2tf(bv1.x)); t1.y = __uint_as_float(f2tf(bv1.y));
        t1.z = __uint_as_float(f2tf(bv1.z)); t1.w = __uint_as_float(f2tf(bv1.w));
        *(float4*)&Bs[0][bk][bnc] = t0;
        *(float4*)&Bs[0][bk][bnc + 4] = t1;
    }
    __syncthreads();

    const int nIter = K / 16;
    for (int it = 0; it < nIter; ++it) {
        if (it + 1 < nIter) {
            Ap += 16;
            Bp += (long)16 * N;
            av0 = *(const float4*)Ap;
            av1 = *(const float4*)(Ap + 4);
            bv0 = *(const float4*)Bp;
            bv1 = *(const float4*)(Bp + 4);
        }
#pragma unroll
        for (int kk = 0; kk < 2; ++kk) {
            const int k = kk * 8;
            unsigned af[4][4];
#pragma unroll
            for (int mt = 0; mt < 4; ++mt) {
                int m = wm * 64 + mt * 16 + (lane >> 2);
                af[mt][0] = __float_as_uint(As[buf][k + (lane & 3)][m]);
                af[mt][1] = __float_as_uint(As[buf][k + (lane & 3)][m + 8]);
                af[mt][2] = __float_as_uint(As[buf][k + (lane & 3) + 4][m]);
                af[mt][3] = __float_as_uint(As[buf][k + (lane & 3) + 4][m + 8]);
            }
#pragma unroll
            for (int nt = 0; nt < 4; ++nt) {
                int n = wn * 32 + nt * 8 + (lane >> 2);
                unsigned b0 = __float_as_uint(Bs[buf][k + (lane & 3)][n]);
                unsigned b1 = __float_as_uint(Bs[buf][k + (lane & 3) + 4][n]);
#pragma unroll
                for (int mt = 0; mt < 4; ++mt)
                    mma_tf32(acc[mt][nt], af[mt][0], af[mt][1], af[mt][2], af[mt][3], b0, b1);
            }
        }
        if (it + 1 < nIter) {
            int nb = buf ^ 1;
            As[nb][ak + 0][ar] = __uint_as_float(f2tf(av0.x));
            As[nb][ak + 1][ar] = __uint_as_float(f2tf(av0.y));
            As[nb][ak + 2][ar] = __uint_as_float(f2tf(av0.z));
            As[nb][ak + 3][ar] = __uint_as_float(f2tf(av0.w));
            As[nb][ak + 4][ar] = __uint_as_float(f2tf(av1.x));
            As[nb][ak + 5][ar] = __uint_as_float(f2tf(av1.y));
            As[nb][ak + 6][ar] = __uint_as_float(f2tf(av1.z));
            As[nb][ak + 7][ar] = __uint_as_float(f2tf(av1.w));
            float4 t0, t1;
            t0.x = __uint_as_float(f2tf(bv0.x)); t0.y = __uint_as_float(f2tf(bv0.y));
            t0.z = __uint_as_float(f2tf(bv0.z)); t0.w = __uint_as_float(f2tf(bv0.w));
            t1.x = __uint_as_float(f2tf(bv1.x)); t1.y = __uint_as_float(f2tf(bv1.y));
            t1.z = __uint_as_float(f2tf(bv1.z)); t1.w = __uint_as_float(f2tf(bv1.w));
            *(float4*)&Bs[nb][bk][bnc] = t0;
            *(float4*)&Bs[nb][bk][bnc + 4] = t1;
            __syncthreads();
            buf = nb;
        }
    }

#pragma unroll
    for (int mt = 0; mt < 4; ++mt) {
        int row0 = bm + wm * 64 + mt * 16 + (lane >> 2);
#pragma unroll
        for (int nt = 0; nt < 4; ++nt) {
            int col = bn + wn * 32 + nt * 8 + 2 * (lane & 3);
            float2 bv = *(const float2*)&bias[col];
            float2 v0, v1;
            v0.x = acc[mt][nt][0] + bv.x; v0.y = acc[mt][nt][1] + bv.y;
            v1.x = acc[mt][nt][2] + bv.x; v1.y = acc[mt][nt][3] + bv.y;
            *(float2*)&C[(long)row0 * N + col] = v0;
            *(float2*)&C[(long)(row0 + 8) * N + col] = v1;
        }
    }
}

// ---------------------------------------------------------------------------
// present = concat(past, new K/V); also emits tf32-rounded copy for attention.
// ---------------------------------------------------------------------------
__global__ __launch_bounds__(256) void copy_present_kernel(
    const float* __restrict__ past, const float* __restrict__ qkv,
    float* __restrict__ present, float* __restrict__ kvt)
{
    int i4 = blockIdx.x * 256 + threadIdx.x;  // 0 .. 4194303
    int d4 = i4 & 15;
    int t = i4 >> 4;
    int p = t & 2047; t >>= 11;
    int h = t & 15;   t >>= 4;
    int b = t & 3;    t >>= 2;
    int kv = t;

    float4 v;
    if (p < 1024) {
        v = *(const float4*)&past[(((long)(kv * 4 + b) * 16 + h) * 1024 + p) * 64 + d4 * 4];
    } else {
        int s = p - 1024;
        v = *(const float4*)&qkv[((long)b * 1024 + s) * 3072 + (kv + 1) * 1024 + h * 64 + d4 * 4];
    }
    *(float4*)&present[(long)i4 * 4] = v;
    float4 r;
    r.x = __uint_as_float(f2tf(v.x));
    r.y = __uint_as_float(f2tf(v.y));
    r.z = __uint_as_float(f2tf(v.z));
    r.w = __uint_as_float(f2tf(v.w));
    *(float4*)&kvt[(long)i4 * 4] = r;
}

// ---------------------------------------------------------------------------
// Flash attention, tf32 mma, cp.async double-buffered K/V, shuffle-P, exp2.
// Block = (b,h,qtile of 128). 8 warps; warp w owns query rows [16w,16w+16).
// ---------------------------------------------------------------------------
#define QKP 68
#define VST 72
#define LOG2E 1.44269504088896f

__global__ __launch_bounds__(256, 2) void attn_kernel(
    const float* __restrict__ qkv,
    const float* __restrict__ kvt,
    float* __restrict__ aout)
{
    extern __shared__ float sm[];
    float* Qs = sm;                         // [128][68]
    float* Ks = Qs + 128 * QKP;             // [2][64][68]
    float* Vs = Ks + 2 * 64 * QKP;          // [2][64][72]

    const int tid = threadIdx.x;
    const int lane = tid & 31;
    const int w = tid >> 5;
    const int qt = blockIdx.x & 7;
    const int h  = (blockIdx.x >> 3) & 15;
    const int b  = blockIdx.x >> 7;

    const float* kbase = kvt + (long)(b * 16 + h) * (2048 * 64);
    const float* vbase = kbase + (long)4 * 16 * 2048 * 64;

    const unsigned ks_base = (unsigned)__cvta_generic_to_shared(Ks);
    const unsigned vs_base = (unsigned)__cvta_generic_to_shared(Vs);

    // thread's cp.async chunk coords: 64 rows x 16 float4 per tile
    const int cr0 = tid >> 2;             // rows tid/4*? -> use idx mapping below

    // Stage Q tile (128 x 64), scale by 0.125*log2e, cvt tf32
    {
        const float* qbase = qkv + ((long)b * 1024 + qt * 128) * 3072 + h * 64;
#pragma unroll
        for (int l = 0; l < 8; ++l) {
            int idx = l * 256 + tid;
            int r = idx >> 4, c = (idx & 15) * 4;
            float4 v = *(const float4*)&qbase[(long)r * 3072 + c];
            const float sc = 0.125f * LOG2E;
            Qs[r * QKP + c + 0] = __uint_as_float(f2tf(v.x * sc));
            Qs[r * QKP + c + 1] = __uint_as_float(f2tf(v.y * sc));
            Qs[r * QKP + c + 2] = __uint_as_float(f2tf(v.z * sc));
            Qs[r * QKP + c + 3] = __uint_as_float(f2tf(v.w * sc));
        }
    }

    const int diag0 = 16 + 2 * qt;
    const int nkt = diag0 + 2;

    // cp.async staging of one K/V tile into buffer bf
    auto stage = [&](int kt, int bf) {
        const float* kp = kbase + (long)kt * 64 * 64;
        const float* vp = vbase + (long)kt * 64 * 64;
        unsigned kd = ks_base + (unsigned)(bf * 64 * QKP * 4);
        unsigned vd = vs_base + (unsigned)(bf * 64 * VST * 4);
#pragma unroll
        for (int l = 0; l < 4; ++l) {
            int idx = l * 256 + tid;          // 1024 chunks of 16B
            int r = idx >> 4, c4 = (idx & 15) * 4;
            cp16(kd + (unsigned)((r * QKP + c4) * 4), kp + idx * 4);
            cp16(vd + (unsigned)((r * VST + c4) * 4), vp + idx * 4);
        }
    };

    stage(0, 0); cp_commit();
    stage(1, 1); cp_commit();
    cp_wait1();          // tile 0 landed (own)
    __syncthreads();     // Q staged + tile 0 visible to all

    // Hoist Q fragments (constant across key tiles)
    unsigned qf[8][4];
    {
        int r = 16 * w + (lane >> 2);
#pragma unroll
        for (int kk = 0; kk < 8; ++kk) {
            int k = kk * 8 + (lane & 3);
            qf[kk][0] = __float_as_uint(Qs[r * QKP + k]);
            qf[kk][1] = __float_as_uint(Qs[(r + 8) * QKP + k]);
            qf[kk][2] = __float_as_uint(Qs[r * QKP + k + 4]);
            qf[kk][3] = __float_as_uint(Qs[(r + 8) * QKP + k + 4]);
        }
    }

    float o[8][4] = {};
    float m0 = -1e30f, m1 = -1e30f, l0 = 0.f, l1 = 0.f;

    const int src_a = (lane & ~3) | ((lane & 3) >> 1);
    const int src_b = src_a + 2;

    for (int kt = 0; kt < nkt; ++kt) {
        const int bf = kt & 1;
        const float* Kb = Ks + bf * 64 * QKP;
        const float* Vb = Vs + bf * 64 * VST;

        // S = Q K^T (log2 domain)
        float s[8][4] = {};
#pragma unroll
        for (int kk = 0; kk < 8; ++kk) {
            int k = kk * 8 + (lane & 3);
#pragma unroll
            for (int nt = 0; nt < 8; ++nt) {
                int n = nt * 8 + (lane >> 2);
                unsigned b0 = __float_as_uint(Kb[n * QKP + k]);
                unsigned b1 = __float_as_uint(Kb[n * QKP + k + 4]);
                mma_tf32(s[nt], qf[kk][0], qf[kk][1], qf[kk][2], qf[kk][3], b0, b1);
            }
        }

        // causal mask (log2 domain constant)
        if (kt >= diag0) {
            int q0 = 1024 + qt * 128 + 16 * w + (lane >> 2);
            int q1 = q0 + 8;
#pragma unroll
            for (int nt = 0; nt < 8; ++nt) {
                int kc = kt * 64 + nt * 8 + 2 * (lane & 3);
                if (kc > q0)     s[nt][0] = -14427.0f;
                if (kc + 1 > q0) s[nt][1] = -14427.0f;
                if (kc > q1)     s[nt][2] = -14427.0f;
                if (kc + 1 > q1) s[nt][3] = -14427.0f;
            }
        }

        // online softmax (exp2)
        {
            float mt0 = -1e30f, mt1 = -1e30f;
#pragma unroll
            for (int nt = 0; nt < 8; ++nt) {
                mt0 = fmaxf(mt0, fmaxf(s[nt][0], s[nt][1]));
                mt1 = fmaxf(mt1, fmaxf(s[nt][2], s[nt][3]));
            }
            mt0 = fmaxf(mt0, __shfl_xor_sync(0xffffffffu, mt0, 1));
            mt0 = fmaxf(mt0, __shfl_xor_sync(0xffffffffu, mt0, 2));
            mt1 = fmaxf(mt1, __shfl_xor_sync(0xffffffffu, mt1, 1));
            mt1 = fmaxf(mt1, __shfl_xor_sync(0xffffffffu, mt1, 2));
            float mn0 = fmaxf(m0, mt0), mn1 = fmaxf(m1, mt1);
            float c0 = ex2(m0 - mn0), c1 = ex2(m1 - mn1);
            m0 = mn0; m1 = mn1;
            float rs0 = 0.f, rs1 = 0.f;
#pragma unroll
            for (int nt = 0; nt < 8; ++nt) {
                s[nt][0] = ex2(s[nt][0] - mn0);
                s[nt][1] = ex2(s[nt][1] - mn0);
                s[nt][2] = ex2(s[nt][2] - mn1);
                s[nt][3] = ex2(s[nt][3] - mn1);
                rs0 += s[nt][0] + s[nt][1];
                rs1 += s[nt][2] + s[nt][3];
            }
            rs0 += __shfl_xor_sync(0xffffffffu, rs0, 1);
            rs0 += __shfl_xor_sync(0xffffffffu, rs0, 2);
            rs1 += __shfl_xor_sync(0xffffffffu, rs1, 1);
            rs1 += __shfl_xor_sync(0xffffffffu, rs1, 2);
            l0 = l0 * c0 + rs0;
            l1 = l1 * c1 + rs1;
#pragma unroll
            for (int dt = 0; dt < 8; ++dt) {
                o[dt][0] *= c0; o[dt][1] *= c0;
                o[dt][2] *= c1; o[dt][3] *= c1;
            }
        }

        // O += P @ V. A-frags built from S C-frags via lane shuffles.
#pragma unroll
        for (int kk = 0; kk < 8; ++kk) {
            float x0 = __shfl_sync(0xffffffffu, s[kk][0], src_a);
            float x1 = __shfl_sync(0xffffffffu, s[kk][1], src_a);
            float y0 = __shfl_sync(0xffffffffu, s[kk][2], src_a);
            float y1 = __shfl_sync(0xffffffffu, s[kk][3], src_a);
            float z0 = __shfl_sync(0xffffffffu, s[kk][0], src_b);
            float z1 = __shfl_sync(0xffffffffu, s[kk][1], src_b);
            float u0 = __shfl_sync(0xffffffffu, s[kk][2], src_b);
            float u1 = __shfl_sync(0xffffffffu, s[kk][3], src_b);
            bool odd = (lane & 1);
            unsigned a0 = f2tf(odd ? x1 : x0);
            unsigned a1 = f2tf(odd ? y1 : y0);
            unsigned a2 = f2tf(odd ? z1 : z0);
            unsigned a3 = f2tf(odd ? u1 : u0);
            int kb0 = (kk * 8 + (lane & 3)) * VST;
            int kb1 = (kk * 8 + (lane & 3) + 4) * VST;
#pragma unroll
            for (int dt = 0; dt < 8; ++dt) {
                int n = dt * 8 + (lane >> 2);
                unsigned b0 = __float_as_uint(Vb[kb0 + n]);
                unsigned b1 = __float_as_uint(Vb[kb1 + n]);
                mma_tf32(o[dt], a0, a1, a2, a3, b0, b1);
            }
        }

        // pipeline maintenance
        if (kt + 1 < nkt) {
            __syncthreads();                    // all done reading buf bf
            if (kt + 2 < nkt) stage(kt + 2, bf);
            cp_commit();                        // (possibly empty) group
            cp_wait1();                         // tile kt+1 landed (own)
            __syncthreads();                    // visible to all
        }
    }

    // epilogue
    {
        float inv0 = 1.0f / l0, inv1 = 1.0f / l1;
        int row0 = b * 1024 + qt * 128 + 16 * w + (lane >> 2);
        float* ob = aout + (long)row0 * 1024 + h * 64;
#pragma unroll
        for (int dt = 0; dt < 8; ++dt) {
            int c = dt * 8 + 2 * (lane & 3);
            float2 v0, v1;
            v0.x = o[dt][0] * inv0; v0.y = o[dt][1] * inv0;
            v1.x = o[dt][2] * inv1; v1.y = o[dt][3] * inv1;
            *(float2*)&ob[c] = v0;
            *(float2*)&ob[(long)8 * 1024 + c] = v1;
        }
    }
}

// ---------------------------------------------------------------------------
extern "C" void kernel_launch(void* const* d_in, const int* in_sizes, int n_in,
                              void* d_out, int out_size)
{
    const float* x      = (const float*)d_in[0];
    const float* past   = (const float*)d_in[1];
    const float* w_attn = (const float*)d_in[2];
    const float* b_attn = (const float*)d_in[3];
    const float* w_proj = (const float*)d_in[4];
    const float* b_proj = (const float*)d_in[5];

    float* out = (float*)d_out;
    float* present = out + 4194304;

    float* qkv_p = nullptr;
    float* attn_p = nullptr;
    float* kvt_p = nullptr;
    cudaGetSymbolAddress((void**)&qkv_p, g_qkv);
    cudaGetSymbolAddress((void**)&attn_p, g_attn);
    cudaGetSymbolAddress((void**)&kvt_p, g_kvt);

    // 1) QKV projection
    {
        dim3 grid(3072 / 128, 4096 / 128);
        gemm_tf32_kernel<<<grid, 256>>>(x, w_attn, b_attn, qkv_p, 4096, 3072, 1024);
    }

    // 2) present + tf32-rounded K/V
    copy_present_kernel<<<4194304 / 256, 256>>>(past, qkv_p, present, kvt_p);

    // 3) attention
    {
        int smem = (128 * QKP + 2 * 64 * QKP + 2 * 64 * VST) * (int)sizeof(float);
        cudaFuncSetAttribute(attn_kernel,
                             cudaFuncAttributeMaxDynamicSharedMemorySize, smem);
        attn_kernel<<<512, 256, smem>>>(qkv_p, kvt_p, attn_p);
    }

    // 4) output projection
    {
        dim3 grid(1024 / 128, 4096 / 128);
        gemm_tf32_kernel<<<grid, 256>>>(attn_p, w_proj, b_proj, out, 4096, 1024, 1024);
    }
}